// round 9
// baseline (speedup 1.0000x reference)
#include <cuda_runtime.h>
#include <cuda_bf16.h>
#include <cstdint>

#define W 512
#define H 512
#define IMGS 128                       // 16 * 8
#define STRIP 32                       // output rows per warp-task
#define STRIPS (H / STRIP)             // 16
#define SEGS 2                         // column segments per row
#define SEGW 256                       // cols per warp segment
#define CPT 8                          // cols per thread
#define TASKS (IMGS * STRIPS * SEGS)   // 4096 warp-tasks
#define BLOCK 256
#define WPB (BLOCK / 32)               // 8
#define GRID (TASKS / WPB)             // 512
#define NELEM 33554432.0f
#define FULLM 0xffffffffu

#define RING 4                         // smem slots per warp
#define DEPTH 3                        // prefetch distance (rows ahead)
#define SLOT 1040                      // bytes per slot: 1024 data + 8 halo + pad

__device__ float g_partials[GRID];
__device__ unsigned int g_count;       // zero-init; last block resets

__device__ __forceinline__ void cp16(unsigned int s, const float* g) {
    asm volatile("cp.async.cg.shared.global [%0], [%1], 16;" :: "r"(s), "l"(g));
}
__device__ __forceinline__ void cp4(unsigned int s, const float* g) {
    asm volatile("cp.async.ca.shared.global [%0], [%1], 4;" :: "r"(s), "l"(g));
}

struct Carry {
    float xp[CPT];    // x[r-1]
    float erp[CPT];   // er[r-1]
    float xLp, xRp;   // halo x (lane0/lane31)
    float erpR;       // er[r-1][c1+1] (lane31)
};

// Compute on row r's data (xc), emit loss for row r-1, advance carry.
__device__ __forceinline__ void step_compute(const float xc[CPT], float xLc, float xRc,
                                             int lane, bool rightEdge,
                                             Carry& C, float& acc) {
    float vm[CPT];
#pragma unroll
    for (int i = 0; i < CPT; i++) vm[i] = fminf(C.xp[i], xc[i]);  // vertical erosion
    float vmL = fminf(C.xLp, xLc);
    float vmR = fminf(C.xRp, xRc);

    // horizontal erosion: er[c] = min(vm[c-1], vm[c])
    float left = __shfl_up_sync(FULLM, vm[CPT-1], 1);
    if (lane == 0) left = vmL;                       // symmetric pad via column clamp
    float ern[CPT];
    ern[0] = fminf(left, vm[0]);
#pragma unroll
    for (int i = 1; i < CPT; i++) ern[i] = fminf(vm[i-1], vm[i]);
    float ernR = fminf(vm[CPT-1], vmR);

    // vertical dilation for row r-1
    float h[CPT];
#pragma unroll
    for (int i = 0; i < CPT; i++) h[i] = fmaxf(C.erp[i], ern[i]);
    float hR = fmaxf(C.erpR, ernR);

    // horizontal dilation + loss
    float hn = __shfl_down_sync(FULLM, h[0], 1);
    if (lane == 31) hn = rightEdge ? h[CPT-1] : hR;  // er[512]=er[511] at image edge
#pragma unroll
    for (int i = 0; i < CPT-1; i++) {
        float di = fmaxf(h[i], h[i+1]);
        float d = C.xp[i] - di;
        acc = fmaf(d, d, acc);
    }
    {
        float di = fmaxf(h[CPT-1], hn);
        float d = C.xp[CPT-1] - di;
        acc = fmaf(d, d, acc);
    }

#pragma unroll
    for (int i = 0; i < CPT; i++) { C.xp[i] = xc[i]; C.erp[i] = ern[i]; }
    C.xLp = xLc; C.xRp = xRc; C.erpR = ernR;
}

__device__ __forceinline__ void final_emit(int lane, bool rightEdge, Carry& C, float& acc) {
    float hn = __shfl_down_sync(FULLM, C.erp[0], 1);
    if (lane == 31) hn = rightEdge ? C.erp[CPT-1] : C.erpR;
#pragma unroll
    for (int i = 0; i < CPT-1; i++) {
        float di = fmaxf(C.erp[i], C.erp[i+1]);
        float d = C.xp[i] - di;
        acc = fmaf(d, d, acc);
    }
    float di = fmaxf(C.erp[CPT-1], hn);
    float d = C.xp[CPT-1] - di;
    acc = fmaf(d, d, acc);
}

__global__ void __launch_bounds__(BLOCK, 4)
opening_loss_kernel(const float* __restrict__ labels, float* __restrict__ out) {
    __shared__ __align__(16) char sring[WPB * RING * SLOT];   // 33280 B

    const int lane = threadIdx.x & 31;
    const int wib  = threadIdx.x >> 5;
    const int warp = blockIdx.x * WPB + wib;
    float acc = 0.0f;

    {
        const int seg   = warp & (SEGS - 1);
        const int t     = warp >> 1;
        const int strip = t & (STRIPS - 1);
        const int img   = t >> 4;                        // STRIPS==16

        const float* base = labels + (size_t)img * (W * H);
        const int r0 = strip * STRIP;
        const int c0 = seg * SEGW;
        const bool rightEdge = (seg == SEGS - 1);
        const int cL = (c0 == 0) ? 0 : c0 - 1;           // clamp == symmetric pad
        const int cR = rightEdge ? (W - 1) : c0 + SEGW;
        const int tcol = c0 + lane * CPT;
        const bool lastStrip = (r0 + STRIP == H);

        char* ringp = sring + wib * (RING * SLOT);
        const unsigned int ring0 = (unsigned int)__cvta_generic_to_shared(ringp);

        // Fetch logical row j (j=0 -> row r0-1 clamped; j=33 max). Tail fetches
        // (j>33) re-fetch row index 33 into a to-be-recycled slot: L1/L2 hits.
        auto fetch = [&](int j) {
            int jj = (j < 33) ? j : 33;
            int rr = r0 - 1 + jj;
            rr = (rr > 0) ? rr : 0;
            rr = (rr < H - 1) ? rr : (H - 1);
            const float* rowb = base + (size_t)rr * W;
            unsigned int slot = ring0 + (unsigned int)(j & (RING - 1)) * SLOT;
            cp16(slot + (unsigned int)lane * 16u,        rowb + tcol);       // x[0..3]
            cp16(slot + 512u + (unsigned int)lane * 16u, rowb + tcol + 4);   // x[4..7]
            if (lane == 0)                cp4(slot + 1024u, rowb + cL);
            if (lane == 31 && !rightEdge) cp4(slot + 1028u, rowb + cR);
            asm volatile("cp.async.commit_group;");
        };

        // Consume logical row j: keep DEPTH rows in flight, then read slot.
        auto consume = [&](int j, float x[CPT], float& xL, float& xR) {
            fetch(j + DEPTH);
            asm volatile("cp.async.wait_group %0;" :: "n"(DEPTH));
            const char* p = ringp + (j & (RING - 1)) * SLOT;
            float4 a = *reinterpret_cast<const float4*>(p + lane * 16);
            float4 b = *reinterpret_cast<const float4*>(p + 512 + lane * 16);
            x[0]=a.x; x[1]=a.y; x[2]=a.z; x[3]=a.w;
            x[4]=b.x; x[5]=b.y; x[6]=b.z; x[7]=b.w;
            xL = (lane == 0)                ? *reinterpret_cast<const float*>(p + 1024) : 0.0f;
            xR = (lane == 31 && !rightEdge) ? *reinterpret_cast<const float*>(p + 1028) : 0.0f;
        };

        // Prime the pipeline.
#pragma unroll
        for (int j = 0; j < DEPTH; j++) fetch(j);

        Carry C;
        // Prologue: rows j=0 (r0-1) and j=1 (r0) -> erp = er[r0], xp = x[r0]
        {
            float xa[CPT], xb[CPT], xLa, xRa, xLb, xRb;
            consume(0, xa, xLa, xRa);
            consume(1, xb, xLb, xRb);

            float vm[CPT];
#pragma unroll
            for (int i = 0; i < CPT; i++) vm[i] = fminf(xa[i], xb[i]);
            float vmL = fminf(xLa, xLb);
            float vmR = fminf(xRa, xRb);

            float left = __shfl_up_sync(FULLM, vm[CPT-1], 1);
            if (lane == 0) left = vmL;
            C.erp[0] = fminf(left, vm[0]);
#pragma unroll
            for (int i = 1; i < CPT; i++) C.erp[i] = fminf(vm[i-1], vm[i]);
            C.erpR = fminf(vm[CPT-1], vmR);
#pragma unroll
            for (int i = 0; i < CPT; i++) C.xp[i] = xb[i];
            C.xLp = xLb; C.xRp = xRb;
        }

        if (!lastStrip) {
#pragma unroll 4
            for (int k = 0; k < STRIP; k++) {
                float xc[CPT], xLc, xRc;
                consume(2 + k, xc, xLc, xRc);
                step_compute(xc, xLc, xRc, lane, rightEdge, C, acc);
            }
        } else {
            for (int k = 0; k < STRIP - 1; k++) {        // rows r0+1 .. 511
                float xc[CPT], xLc, xRc;
                consume(2 + k, xc, xLc, xRc);
                step_compute(xc, xLc, xRc, lane, rightEdge, C, acc);
            }
            final_emit(lane, rightEdge, C, acc);
        }
        asm volatile("cp.async.wait_group 0;");          // drain before smem reuse/exit
    }

    // Deterministic block reduction
#pragma unroll
    for (int off = 16; off; off >>= 1)
        acc += __shfl_xor_sync(FULLM, acc, off);

    __shared__ float s[WPB];
    __shared__ bool is_last;
    if (lane == 0) s[wib] = acc;
    __syncthreads();
    if (threadIdx.x == 0) {
        float tsum = 0.0f;
#pragma unroll
        for (int i = 0; i < WPB; i++) tsum += s[i];
        g_partials[blockIdx.x] = tsum;
        __threadfence();
        unsigned v = atomicAdd(&g_count, 1u);
        is_last = (v == GRID - 1);
    }
    __syncthreads();

    // Last block: deterministic final tree reduction over 512 partials.
    if (is_last) {
        __shared__ float r[BLOCK];
        r[threadIdx.x] = g_partials[threadIdx.x] + g_partials[threadIdx.x + BLOCK];
        __syncthreads();
#pragma unroll
        for (int off = BLOCK / 2; off > 0; off >>= 1) {
            if (threadIdx.x < off) r[threadIdx.x] += r[threadIdx.x + off];
            __syncthreads();
        }
        if (threadIdx.x == 0) {
            out[0] = r[0] * (1.0f / NELEM);
            g_count = 0;    // reset for graph replay
        }
    }
}

extern "C" void kernel_launch(void* const* d_in, const int* in_sizes, int n_in,
                              void* d_out, int out_size) {
    const float* labels = (const float*)d_in[0];
    float* out = (float*)d_out;
    opening_loss_kernel<<<GRID, BLOCK>>>(labels, out);
}